// round 13
// baseline (speedup 1.0000x reference)
#include <cuda_runtime.h>
#include <cstdint>
#include <cstddef>

#define BATCH 2048
#define NN    14
#define INF   2048
#define OUTF  1024
#define MROWS (BATCH * NN)
#define WN    (2 * OUTF)

#define KT         16
#define A2_STRIDE  130   // u64 elems per k-plane row array (16B-aligned stride)
// dynamic smem: As2[2][KT][A2_STRIDE] u64  +  Bs[2][KT][128] f32
#define A2_BYTES   (2 * KT * A2_STRIDE * 8)
#define SMEM_BYTES (A2_BYTES + 2 * KT * 128 * 4)

// CPU (MXCSR FTZ) emulation: nonnegative tiny values below FLT_MIN -> 0.
__device__ __forceinline__ float ftzf(float x) {
    return (x < 1.17549435e-38f) ? 0.f : x;
}

// Packed fp32 FMA (Blackwell f32x2). Each lane is an independent IEEE fp32
// fma.rn -> bitwise identical to two scalar fmaf chains.
__device__ __forceinline__ void ffma2(unsigned long long& d,
                                      unsigned long long a,
                                      unsigned long long b) {
    asm("fma.rn.f32x2 %0, %1, %2, %0;" : "+l"(d) : "l"(a), "l"(b));
}
__device__ __forceinline__ unsigned long long dup2(float x) {
    unsigned long long r;
    asm("mov.b64 %0, {%1, %1};" : "=l"(r) : "r"(__float_as_uint(x)));
    return r;
}
__device__ __forceinline__ float lo32(unsigned long long v) {
    return __uint_as_float((unsigned)(v & 0xffffffffull));
}
__device__ __forceinline__ float hi32(unsigned long long v) {
    return __uint_as_float((unsigned)(v >> 32));
}

__device__ float g_Wpack[INF * WN];
__device__ float g_bpack[WN];
__device__ float g_Y1[MROWS * WN];
__device__ float g_Y2[MROWS * WN];
__device__ float g_e1[MROWS * OUTF];
__device__ float g_e2[MROWS * OUTF];
__device__ float g_M1[MROWS * OUTF];

__global__ void pack_w_kernel(const float* __restrict__ aw, const float* __restrict__ ab,
                              const float* __restrict__ uw, const float* __restrict__ ub)
{
    int idx = blockIdx.x * blockDim.x + threadIdx.x;
    if (idx < INF * OUTF) {
        int k = idx >> 10, n = idx & 1023;
        g_Wpack[k * WN + n]        = aw[idx];
        g_Wpack[k * WN + OUTF + n] = uw[idx];
    }
    if (idx < OUTF) { g_bpack[idx] = ab[idx]; g_bpack[OUTF + idx] = ub[idx]; }
}

// fp32 SGEMM, sequential-k accumulation per output element (bitwise equal to
// an ascending-k fmaf chain). f32x2-packed over N columns. A is stored
// PRE-DUPLICATED in shared as (a,a) u64 per row: A is the broadcast operand
// (16 lanes read the same address), so per-kk A loads are 1-phase LDS.128s,
// and the per-kk dup2 ALU hop is gone -> direct LDS->FFMA2 dependencies.
// B pairs load directly from plain Bs (adjacent floats = packed pair).
// 128x128 tile, K-tile 16, 256 threads, 8x8 outputs/thread, double-buffered.
__global__ __launch_bounds__(256, 2)
void sgemm_kernel(const float* __restrict__ A, const float* __restrict__ B,
                  float* __restrict__ C, int K, int N,
                  const float* __restrict__ bias, int do_relu)
{
    extern __shared__ __align__(16) char smem[];
    typedef unsigned long long u64;
    u64   (*As2)[KT][A2_STRIDE] = (u64 (*)[KT][A2_STRIDE])smem;
    float (*Bs)[KT][128]        = (float (*)[KT][128])(smem + A2_BYTES);

    const int tid = threadIdx.x, bm = blockIdx.y, bn = blockIdx.x;
    const float* Ab = A + (size_t)bm * 128 * K;
    const float* Bb = B + (size_t)bn * 128;

    const int arow = tid >> 2, acol = (tid & 3) * 4;
    const int brow = tid >> 5, bcol = (tid & 31) * 4;
    const int tx = tid & 15, ty = tid >> 4;

    // acc2[i][jp]: row i (0..3 -> ty*4+i, 4..7 -> 64+ty*4+i-4),
    // jp: 0 -> cols tx*4+0(lo),+1(hi); 1 -> +2,+3; 2 -> 64+tx*4+0,+1; 3 -> +2,+3
    u64 acc2[8][4];
#pragma unroll
    for (int i = 0; i < 8; i++)
#pragma unroll
        for (int j = 0; j < 4; j++) acc2[i][j] = 0ull;

    const int nk = K >> 4;

    // prologue: tile 0
    {
        float4 a0 = *(const float4*)(Ab + (size_t)arow * K + acol);
        float4 a1 = *(const float4*)(Ab + (size_t)(arow + 64) * K + acol);
        float4 b0 = *(const float4*)(Bb + (size_t)brow * N + bcol);
        float4 b1 = *(const float4*)(Bb + (size_t)(brow + 8) * N + bcol);
        As2[0][acol+0][arow] = dup2(a0.x); As2[0][acol+1][arow] = dup2(a0.y);
        As2[0][acol+2][arow] = dup2(a0.z); As2[0][acol+3][arow] = dup2(a0.w);
        As2[0][acol+0][arow+64] = dup2(a1.x); As2[0][acol+1][arow+64] = dup2(a1.y);
        As2[0][acol+2][arow+64] = dup2(a1.z); As2[0][acol+3][arow+64] = dup2(a1.w);
        *(float4*)&Bs[0][brow][bcol]     = b0;
        *(float4*)&Bs[0][brow + 8][bcol] = b1;
    }
    __syncthreads();

    for (int kt = 0; kt < nk; kt++) {
        const int cur = kt & 1, nxt = cur ^ 1;
        float4 na0, na1, nb0, nb1;
        const bool has_next = (kt + 1 < nk);
        if (has_next) {
            const float* Ap = Ab + (size_t)(kt + 1) * 16;
            const float* Bp = Bb + (size_t)(kt + 1) * 16 * N;
            na0 = *(const float4*)(Ap + (size_t)arow * K + acol);
            na1 = *(const float4*)(Ap + (size_t)(arow + 64) * K + acol);
            nb0 = *(const float4*)(Bp + (size_t)brow * N + bcol);
            nb1 = *(const float4*)(Bp + (size_t)(brow + 8) * N + bcol);
        }
#pragma unroll
        for (int kk = 0; kk < 16; kk++) {
            // A dup pairs: 16-lane broadcast LDS.128s (1 phase each).
            ulonglong2 a01 = *(const ulonglong2*)&As2[cur][kk][ty * 4];
            ulonglong2 a23 = *(const ulonglong2*)&As2[cur][kk][ty * 4 + 2];
            ulonglong2 a45 = *(const ulonglong2*)&As2[cur][kk][64 + ty * 4];
            ulonglong2 a67 = *(const ulonglong2*)&As2[cur][kk][64 + ty * 4 + 2];
            // B packed pairs straight from plain Bs.
            ulonglong2 bA = *(const ulonglong2*)&Bs[cur][kk][tx * 4];
            ulonglong2 bB = *(const ulonglong2*)&Bs[cur][kk][64 + tx * 4];
            u64 ap[8] = { a01.x, a01.y, a23.x, a23.y, a45.x, a45.y, a67.x, a67.y };
            u64 bp[4] = { bA.x, bA.y, bB.x, bB.y };
#pragma unroll
            for (int i = 0; i < 8; i++)
#pragma unroll
                for (int j = 0; j < 4; j++)
                    ffma2(acc2[i][j], ap[i], bp[j]);
        }
        if (has_next) {
            As2[nxt][acol+0][arow] = dup2(na0.x); As2[nxt][acol+1][arow] = dup2(na0.y);
            As2[nxt][acol+2][arow] = dup2(na0.z); As2[nxt][acol+3][arow] = dup2(na0.w);
            As2[nxt][acol+0][arow+64] = dup2(na1.x); As2[nxt][acol+1][arow+64] = dup2(na1.y);
            As2[nxt][acol+2][arow+64] = dup2(na1.z); As2[nxt][acol+3][arow+64] = dup2(na1.w);
            *(float4*)&Bs[nxt][brow][bcol]     = nb0;
            *(float4*)&Bs[nxt][brow + 8][bcol] = nb1;
            __syncthreads();
        }
    }

    const int row0 = bm * 128, col0 = bn * 128;
    float bb[8];
    if (bias) {
#pragma unroll
        for (int j = 0; j < 4; j++) {
            bb[j]     = bias[col0 + tx * 4 + j];
            bb[4 + j] = bias[col0 + 64 + tx * 4 + j];
        }
    } else {
#pragma unroll
        for (int j = 0; j < 8; j++) bb[j] = 0.f;
    }
#pragma unroll
    for (int i = 0; i < 8; i++) {
        const int m = (i < 4) ? (ty * 4 + i) : (64 + ty * 4 + (i - 4));
        float* Crow = C + (size_t)(row0 + m) * N + col0;
        float v[8];
        v[0] = lo32(acc2[i][0]); v[1] = hi32(acc2[i][0]);
        v[2] = lo32(acc2[i][1]); v[3] = hi32(acc2[i][1]);
        v[4] = lo32(acc2[i][2]); v[5] = hi32(acc2[i][2]);
        v[6] = lo32(acc2[i][3]); v[7] = hi32(acc2[i][3]);
#pragma unroll
        for (int j = 0; j < 8; j++) {
            float x = __fadd_rn(v[j], bb[j]);
            v[j] = do_relu ? fmaxf(x, 0.f) : x;
        }
        *(float4*)(Crow + tx * 4)      = make_float4(v[0], v[1], v[2], v[3]);
        *(float4*)(Crow + 64 + tx * 4) = make_float4(v[4], v[5], v[6], v[7]);
    }
}

// Gconv: e = bmm(Anorm, AX) + UX (dot from zero, then elementwise add).
__global__ void gconv_kernel(const float* __restrict__ adj, const float* __restrict__ Y,
                             float* __restrict__ e)
{
    const int b = blockIdx.x, tid = threadIdx.x;
    __shared__ float sA[NN * NN];
    __shared__ float cs[NN];
    __shared__ float An[NN][NN + 2];

    if (tid < NN * NN) sA[tid] = adj[(size_t)b * NN * NN + tid];
    __syncthreads();
    if (tid < NN) {
        float s = 0.f;
#pragma unroll
        for (int i = 0; i < NN; i++) s = __fadd_rn(s, sA[i * NN + tid]);
        cs[tid] = fmaxf(s, 1e-12f);
    }
    __syncthreads();
    if (tid < NN * NN) {
        int i = tid / NN, j = tid - i * NN;
        An[i][j] = __fdiv_rn(sA[tid], cs[j]);
    }
    __syncthreads();

    const float* Yb = Y + (size_t)b * NN * WN;
    float* eb = e + (size_t)b * NN * OUTF;
    for (int f = tid; f < OUTF; f += blockDim.x) {
        float ax[NN], ux[NN];
#pragma unroll
        for (int j = 0; j < NN; j++) {
            ax[j] = Yb[j * WN + f];
            ux[j] = Yb[j * WN + OUTF + f];
        }
#pragma unroll
        for (int i = 0; i < NN; i++) {
            float d = __fmul_rn(An[i][0], ax[0]);
#pragma unroll
            for (int j = 1; j < NN; j++) d = fmaf(An[i][j], ax[j], d);
            eb[i * OUTF + f] = __fadd_rn(d, ux[i]);
        }
    }
}

// Affinity gram (sequential fp32) + softmax(200*s) + 20 Sinkhorn iters with
// FTZ emulation at every tiny-value production site.
__global__ void affinity_kernel(const float* __restrict__ Mx, const float* __restrict__ E2,
                                float* __restrict__ s_out)
{
    const int b = blockIdx.x, tid = threadIdx.x;
    __shared__ float sM[NN][129];
    __shared__ float sE[NN][129];
    __shared__ float S[NN][NN + 1];

    const float* Mb = Mx + (size_t)b * NN * OUTF;
    const float* Eb = E2 + (size_t)b * NN * OUTF;
    const int i = tid / NN, j = tid - i * NN;
    float acc = 0.f;

    for (int d0 = 0; d0 < OUTF; d0 += 128) {
        for (int t = tid; t < NN * 128; t += 256) {
            int r = t >> 7, c = t & 127;
            sM[r][c] = Mb[r * OUTF + d0 + c];
            sE[r][c] = Eb[r * OUTF + d0 + c];
        }
        __syncthreads();
        if (tid < NN * NN) {
#pragma unroll 8
            for (int c = 0; c < 128; c++)
                acc = fmaf(sM[i][c], sE[j][c], acc);
        }
        __syncthreads();
    }
    if (tid < NN * NN) S[i][j] = acc;
    __syncthreads();

    if (tid < NN) {
        float t[NN], m = -__int_as_float(0x7f800000);
#pragma unroll
        for (int jj = 0; jj < NN; jj++) {
            t[jj] = __fmul_rn(200.f, S[tid][jj]);
            m = fmaxf(m, t[jj]);
        }
        float p[NN], sum = 0.f;
#pragma unroll
        for (int jj = 0; jj < NN; jj++) {
            p[jj] = ftzf(expf(__fadd_rn(t[jj], -m)));
            sum = __fadd_rn(sum, p[jj]);
        }
#pragma unroll
        for (int jj = 0; jj < NN; jj++)
            S[tid][jj] = ftzf(__fdiv_rn(p[jj], sum));
    }
    __syncthreads();

    for (int it = 0; it < 20; it++) {
        if ((it & 1) == 0) {
            if (tid < NN) {
                float sum = 0.f;
#pragma unroll
                for (int jj = 0; jj < NN; jj++) sum = __fadd_rn(sum, S[tid][jj]);
                sum = __fadd_rn(sum, 1e-10f);
#pragma unroll
                for (int jj = 0; jj < NN; jj++)
                    S[tid][jj] = ftzf(__fdiv_rn(S[tid][jj], sum));
            }
        } else {
            if (tid < NN) {
                float sum = 0.f;
#pragma unroll
                for (int ii = 0; ii < NN; ii++) sum = __fadd_rn(sum, S[ii][tid]);
                sum = __fadd_rn(sum, 1e-10f);
#pragma unroll
                for (int ii = 0; ii < NN; ii++)
                    S[ii][tid] = ftzf(__fdiv_rn(S[ii][tid], sum));
            }
        }
        __syncthreads();
    }
    if (tid < NN * NN) s_out[(size_t)b * NN * NN + tid] = S[i][j];
}

// Fusion: dot from zero over the contraction index, then add feat.
__global__ void fuse_kernel(const float* __restrict__ f1, const float* __restrict__ f2,
                            const float* __restrict__ s,
                            float* __restrict__ o1, float* __restrict__ o2)
{
    const int b = blockIdx.y;
    const int f = blockIdx.x * blockDim.x + threadIdx.x;
    __shared__ float S[NN * NN];
    if (threadIdx.x < NN * NN) S[threadIdx.x] = s[(size_t)b * NN * NN + threadIdx.x];
    __syncthreads();

    const float* f1b = f1 + (size_t)b * NN * INF;
    const float* f2b = f2 + (size_t)b * NN * INF;
    float* o1b = o1 + (size_t)b * NN * INF;
    float* o2b = o2 + (size_t)b * NN * INF;

    float x1[NN], x2[NN];
#pragma unroll
    for (int r = 0; r < NN; r++) { x1[r] = f1b[r * INF + f]; x2[r] = f2b[r * INF + f]; }
#pragma unroll
    for (int i = 0; i < NN; i++) {
        float d = __fmul_rn(S[i * NN], x2[0]);
#pragma unroll
        for (int jj = 1; jj < NN; jj++) d = fmaf(S[i * NN + jj], x2[jj], d);
        o1b[i * INF + f] = __fadd_rn(x1[i], d);
    }
#pragma unroll
    for (int jj = 0; jj < NN; jj++) {
        float d = __fmul_rn(S[jj], x1[0]);
#pragma unroll
        for (int ii = 1; ii < NN; ii++) d = fmaf(S[ii * NN + jj], x1[ii], d);
        o2b[jj * INF + f] = __fadd_rn(x2[jj], d);
    }
}

static float* symaddr(const void* sym) {
    void* p = nullptr;
    cudaGetSymbolAddress(&p, sym);
    return (float*)p;
}

extern "C" void kernel_launch(void* const* d_in, const int* in_sizes, int n_in,
                              void* d_out, int out_size)
{
    const float* feat1  = (const float*)d_in[0];
    const float* feat2  = (const float*)d_in[1];
    const float* adj    = (const float*)d_in[2];
    const float* a_fc_w = (const float*)d_in[3];
    const float* a_fc_b = (const float*)d_in[4];
    const float* u_fc_w = (const float*)d_in[5];
    const float* u_fc_b = (const float*)d_in[6];
    const float* aff_A  = (const float*)d_in[7];

    float* out   = (float*)d_out;
    float* s_out = out;
    float* out1  = out + (size_t)BATCH * NN * NN;
    float* out2  = out1 + (size_t)BATCH * NN * INF;

    float* Wp = symaddr(g_Wpack);
    float* bp = symaddr(g_bpack);
    float* Y1 = symaddr(g_Y1);
    float* Y2 = symaddr(g_Y2);
    float* e1 = symaddr(g_e1);
    float* e2 = symaddr(g_e2);
    float* M1 = symaddr(g_M1);

    // Allow ~48.5KB dynamic smem (host attribute, not a stream op; idempotent).
    cudaFuncSetAttribute(sgemm_kernel,
                         cudaFuncAttributeMaxDynamicSharedMemorySize, SMEM_BYTES);

    pack_w_kernel<<<(INF * OUTF + 255) / 256, 256>>>(a_fc_w, a_fc_b, u_fc_w, u_fc_b);

    // Y GEMMs split into M-halves so the ncu capture slot lands on sgemm.
    const int MH = MROWS / 2;
    dim3 gh(WN / 128, MH / 128);
    sgemm_kernel<<<gh, 256, SMEM_BYTES>>>(feat1,                    Wp, Y1,                   INF, WN, bp, 1);
    sgemm_kernel<<<gh, 256, SMEM_BYTES>>>(feat1 + (size_t)MH * INF, Wp, Y1 + (size_t)MH * WN, INF, WN, bp, 1);
    sgemm_kernel<<<gh, 256, SMEM_BYTES>>>(feat2,                    Wp, Y2,                   INF, WN, bp, 1);
    sgemm_kernel<<<gh, 256, SMEM_BYTES>>>(feat2 + (size_t)MH * INF, Wp, Y2 + (size_t)MH * WN, INF, WN, bp, 1);

    gconv_kernel<<<BATCH, 256>>>(adj, Y1, e1);
    gconv_kernel<<<BATCH, 256>>>(adj, Y2, e2);

    dim3 g2(OUTF / 128, MROWS / 128);
    sgemm_kernel<<<g2, 256, SMEM_BYTES>>>(e1, aff_A, M1, OUTF, OUTF, nullptr, 0);

    affinity_kernel<<<BATCH, 256>>>(M1, e2, s_out);

    dim3 g3(INF / 256, BATCH);
    fuse_kernel<<<g3, 256>>>(feat1, feat2, s_out, out1, out2);
}

// round 14
// speedup vs baseline: 1.1301x; 1.1301x over previous
#include <cuda_runtime.h>
#include <cstdint>
#include <cstddef>

#define BATCH 2048
#define NN    14
#define INF   2048
#define OUTF  1024
#define MROWS (BATCH * NN)
#define WN    (2 * OUTF)

// CPU (MXCSR FTZ) emulation: nonnegative tiny values below FLT_MIN -> 0.
__device__ __forceinline__ float ftzf(float x) {
    return (x < 1.17549435e-38f) ? 0.f : x;
}

// Packed fp32 FMA (Blackwell f32x2). Each lane is an independent IEEE fp32
// fma.rn -> bitwise identical to two scalar fmaf chains.
__device__ __forceinline__ void ffma2(unsigned long long& d,
                                      unsigned long long a,
                                      unsigned long long b) {
    asm("fma.rn.f32x2 %0, %1, %2, %0;" : "+l"(d) : "l"(a), "l"(b));
}
__device__ __forceinline__ unsigned long long dup2(float x) {
    unsigned long long r;
    asm("mov.b64 %0, {%1, %1};" : "=l"(r) : "r"(__float_as_uint(x)));
    return r;
}
__device__ __forceinline__ float lo32(unsigned long long v) {
    return __uint_as_float((unsigned)(v & 0xffffffffull));
}
__device__ __forceinline__ float hi32(unsigned long long v) {
    return __uint_as_float((unsigned)(v >> 32));
}

__device__ float g_Wpack[INF * WN];
__device__ float g_bpack[WN];
__device__ float g_Y1[MROWS * WN];
__device__ float g_Y2[MROWS * WN];
__device__ float g_e1[MROWS * OUTF];
__device__ float g_e2[MROWS * OUTF];
__device__ float g_M1[MROWS * OUTF];

__global__ void pack_w_kernel(const float* __restrict__ aw, const float* __restrict__ ab,
                              const float* __restrict__ uw, const float* __restrict__ ub)
{
    int idx = blockIdx.x * blockDim.x + threadIdx.x;
    if (idx < INF * OUTF) {
        int k = idx >> 10, n = idx & 1023;
        g_Wpack[k * WN + n]        = aw[idx];
        g_Wpack[k * WN + OUTF + n] = uw[idx];
    }
    if (idx < OUTF) { g_bpack[idx] = ab[idx]; g_bpack[OUTF + idx] = ub[idx]; }
}

// fp32 SGEMM, sequential-k accumulation per output element (bitwise equal to
// an ascending-k fmaf chain). f32x2 M-packed: two M-rows per u64 accumulator,
// A row-pairs load directly from As as aligned u64 pairs (no dup), B scalars
// dup'd via 4 ALU movs/kk. 128x64 tile, K-tile 16, 256 threads, 8x4 outputs
// per thread, 3 CTAs/SM (24 warps = 6/SMSP for LDS latency hiding).
__global__ __launch_bounds__(256, 3)
void sgemm_kernel(const float* __restrict__ A, const float* __restrict__ B,
                  float* __restrict__ C, int K, int N,
                  const float* __restrict__ bias, int do_relu)
{
    __shared__ __align__(16) float As[2][16][132];   // [k][row]
    __shared__ __align__(16) float Bs[2][16][64];    // [k][col]

    const int tid = threadIdx.x, bm = blockIdx.y, bn = blockIdx.x;
    const float* Ab = A + (size_t)bm * 128 * K;
    const float* Bb = B + (size_t)bn * 64;

    // A loader: rows (arow, arow+64), float4 at acol (K-tile 16)
    const int arow = tid >> 2, acol = (tid & 3) * 4;
    // B loader: 16 k-rows x 64 cols, one float4 per thread
    const int brow = tid >> 4, bcol = (tid & 15) * 4;

    const int tx = tid & 15, ty = tid >> 4;

    // acc2[i2][j]: i2=0 -> rows ty*4+0(lo),+1(hi); i2=1 -> +2,+3;
    //             i2=2 -> 64+ty*4+0,+1;           i2=3 -> 64+ty*4+2,+3
    // j = col tx*4+j
    unsigned long long acc2[4][4];
#pragma unroll
    for (int i = 0; i < 4; i++)
#pragma unroll
        for (int j = 0; j < 4; j++) acc2[i][j] = 0ull;

    const int nk = K >> 4;

    // prologue: tile 0
    {
        float4 a0 = *(const float4*)(Ab + (size_t)arow * K + acol);
        float4 a1 = *(const float4*)(Ab + (size_t)(arow + 64) * K + acol);
        float4 b0 = *(const float4*)(Bb + (size_t)brow * N + bcol);
        As[0][acol+0][arow] = a0.x; As[0][acol+1][arow] = a0.y;
        As[0][acol+2][arow] = a0.z; As[0][acol+3][arow] = a0.w;
        As[0][acol+0][arow+64] = a1.x; As[0][acol+1][arow+64] = a1.y;
        As[0][acol+2][arow+64] = a1.z; As[0][acol+3][arow+64] = a1.w;
        *(float4*)&Bs[0][brow][bcol] = b0;
    }
    __syncthreads();

    for (int kt = 0; kt < nk; kt++) {
        const int cur = kt & 1, nxt = cur ^ 1;
        float4 na0, na1, nb0;
        const bool has_next = (kt + 1 < nk);
        if (has_next) {
            const float* Ap = Ab + (size_t)(kt + 1) * 16;
            const float* Bp = Bb + (size_t)(kt + 1) * 16 * N;
            na0 = *(const float4*)(Ap + (size_t)arow * K + acol);
            na1 = *(const float4*)(Ap + (size_t)(arow + 64) * K + acol);
            nb0 = *(const float4*)(Bp + (size_t)brow * N + bcol);
        }
#pragma unroll
        for (int kk = 0; kk < 16; kk++) {
            // A row pairs: 16B-aligned (row stride 132 floats = 528B).
            ulonglong2 aA = *(const ulonglong2*)&As[cur][kk][ty * 4];
            ulonglong2 aB = *(const ulonglong2*)&As[cur][kk][64 + ty * 4];
            float4 b = *(const float4*)&Bs[cur][kk][tx * 4];
            unsigned long long ap[4] = { aA.x, aA.y, aB.x, aB.y };
            unsigned long long bp[4] = { dup2(b.x), dup2(b.y), dup2(b.z), dup2(b.w) };
#pragma unroll
            for (int i = 0; i < 4; i++)
#pragma unroll
                for (int j = 0; j < 4; j++)
                    ffma2(acc2[i][j], ap[i], bp[j]);
        }
        if (has_next) {
            As[nxt][acol+0][arow] = na0.x; As[nxt][acol+1][arow] = na0.y;
            As[nxt][acol+2][arow] = na0.z; As[nxt][acol+3][arow] = na0.w;
            As[nxt][acol+0][arow+64] = na1.x; As[nxt][acol+1][arow+64] = na1.y;
            As[nxt][acol+2][arow+64] = na1.z; As[nxt][acol+3][arow+64] = na1.w;
            *(float4*)&Bs[nxt][brow][bcol] = nb0;
            __syncthreads();
        }
    }

    const int row0 = bm * 128, col0 = bn * 64;
    float bb[4];
#pragma unroll
    for (int j = 0; j < 4; j++) bb[j] = bias ? bias[col0 + tx * 4 + j] : 0.f;

#pragma unroll
    for (int i = 0; i < 8; i++) {
        const int half = i >> 2;          // 0: rows ty*4+, 1: rows 64+ty*4+
        const int r    = i & 3;           // row within half
        const int i2   = half * 2 + (r >> 1);
        const int lane = r & 1;
        const int m = half * 64 + ty * 4 + r;
        float* Crow = C + (size_t)(row0 + m) * N + col0;
        float v[4];
#pragma unroll
        for (int j = 0; j < 4; j++) {
            float part = lane ? hi32(acc2[i2][j]) : lo32(acc2[i2][j]);
            float x = __fadd_rn(part, bb[j]);
            v[j] = do_relu ? fmaxf(x, 0.f) : x;
        }
        *(float4*)(Crow + tx * 4) = make_float4(v[0], v[1], v[2], v[3]);
    }
}

// Gconv: e = bmm(Anorm, AX) + UX (dot from zero, then elementwise add).
__global__ void gconv_kernel(const float* __restrict__ adj, const float* __restrict__ Y,
                             float* __restrict__ e)
{
    const int b = blockIdx.x, tid = threadIdx.x;
    __shared__ float sA[NN * NN];
    __shared__ float cs[NN];
    __shared__ float An[NN][NN + 2];

    if (tid < NN * NN) sA[tid] = adj[(size_t)b * NN * NN + tid];
    __syncthreads();
    if (tid < NN) {
        float s = 0.f;
#pragma unroll
        for (int i = 0; i < NN; i++) s = __fadd_rn(s, sA[i * NN + tid]);
        cs[tid] = fmaxf(s, 1e-12f);
    }
    __syncthreads();
    if (tid < NN * NN) {
        int i = tid / NN, j = tid - i * NN;
        An[i][j] = __fdiv_rn(sA[tid], cs[j]);
    }
    __syncthreads();

    const float* Yb = Y + (size_t)b * NN * WN;
    float* eb = e + (size_t)b * NN * OUTF;
    for (int f = tid; f < OUTF; f += blockDim.x) {
        float ax[NN], ux[NN];
#pragma unroll
        for (int j = 0; j < NN; j++) {
            ax[j] = Yb[j * WN + f];
            ux[j] = Yb[j * WN + OUTF + f];
        }
#pragma unroll
        for (int i = 0; i < NN; i++) {
            float d = __fmul_rn(An[i][0], ax[0]);
#pragma unroll
            for (int j = 1; j < NN; j++) d = fmaf(An[i][j], ax[j], d);
            eb[i * OUTF + f] = __fadd_rn(d, ux[i]);
        }
    }
}

// Affinity gram (sequential fp32) + softmax(200*s) + 20 Sinkhorn iters with
// FTZ emulation at every tiny-value production site.
__global__ void affinity_kernel(const float* __restrict__ Mx, const float* __restrict__ E2,
                                float* __restrict__ s_out)
{
    const int b = blockIdx.x, tid = threadIdx.x;
    __shared__ float sM[NN][129];
    __shared__ float sE[NN][129];
    __shared__ float S[NN][NN + 1];

    const float* Mb = Mx + (size_t)b * NN * OUTF;
    const float* Eb = E2 + (size_t)b * NN * OUTF;
    const int i = tid / NN, j = tid - i * NN;
    float acc = 0.f;

    for (int d0 = 0; d0 < OUTF; d0 += 128) {
        for (int t = tid; t < NN * 128; t += 256) {
            int r = t >> 7, c = t & 127;
            sM[r][c] = Mb[r * OUTF + d0 + c];
            sE[r][c] = Eb[r * OUTF + d0 + c];
        }
        __syncthreads();
        if (tid < NN * NN) {
#pragma unroll 8
            for (int c = 0; c < 128; c++)
                acc = fmaf(sM[i][c], sE[j][c], acc);
        }
        __syncthreads();
    }
    if (tid < NN * NN) S[i][j] = acc;
    __syncthreads();

    if (tid < NN) {
        float t[NN], m = -__int_as_float(0x7f800000);
#pragma unroll
        for (int jj = 0; jj < NN; jj++) {
            t[jj] = __fmul_rn(200.f, S[tid][jj]);
            m = fmaxf(m, t[jj]);
        }
        float p[NN], sum = 0.f;
#pragma unroll
        for (int jj = 0; jj < NN; jj++) {
            p[jj] = ftzf(expf(__fadd_rn(t[jj], -m)));
            sum = __fadd_rn(sum, p[jj]);
        }
#pragma unroll
        for (int jj = 0; jj < NN; jj++)
            S[tid][jj] = ftzf(__fdiv_rn(p[jj], sum));
    }
    __syncthreads();

    for (int it = 0; it < 20; it++) {
        if ((it & 1) == 0) {
            if (tid < NN) {
                float sum = 0.f;
#pragma unroll
                for (int jj = 0; jj < NN; jj++) sum = __fadd_rn(sum, S[tid][jj]);
                sum = __fadd_rn(sum, 1e-10f);
#pragma unroll
                for (int jj = 0; jj < NN; jj++)
                    S[tid][jj] = ftzf(__fdiv_rn(S[tid][jj], sum));
            }
        } else {
            if (tid < NN) {
                float sum = 0.f;
#pragma unroll
                for (int ii = 0; ii < NN; ii++) sum = __fadd_rn(sum, S[ii][tid]);
                sum = __fadd_rn(sum, 1e-10f);
#pragma unroll
                for (int ii = 0; ii < NN; ii++)
                    S[ii][tid] = ftzf(__fdiv_rn(S[ii][tid], sum));
            }
        }
        __syncthreads();
    }
    if (tid < NN * NN) s_out[(size_t)b * NN * NN + tid] = S[i][j];
}

// Fusion: dot from zero over the contraction index, then add feat.
__global__ void fuse_kernel(const float* __restrict__ f1, const float* __restrict__ f2,
                            const float* __restrict__ s,
                            float* __restrict__ o1, float* __restrict__ o2)
{
    const int b = blockIdx.y;
    const int f = blockIdx.x * blockDim.x + threadIdx.x;
    __shared__ float S[NN * NN];
    if (threadIdx.x < NN * NN) S[threadIdx.x] = s[(size_t)b * NN * NN + threadIdx.x];
    __syncthreads();

    const float* f1b = f1 + (size_t)b * NN * INF;
    const float* f2b = f2 + (size_t)b * NN * INF;
    float* o1b = o1 + (size_t)b * NN * INF;
    float* o2b = o2 + (size_t)b * NN * INF;

    float x1[NN], x2[NN];
#pragma unroll
    for (int r = 0; r < NN; r++) { x1[r] = f1b[r * INF + f]; x2[r] = f2b[r * INF + f]; }
#pragma unroll
    for (int i = 0; i < NN; i++) {
        float d = __fmul_rn(S[i * NN], x2[0]);
#pragma unroll
        for (int jj = 1; jj < NN; jj++) d = fmaf(S[i * NN + jj], x2[jj], d);
        o1b[i * INF + f] = __fadd_rn(x1[i], d);
    }
#pragma unroll
    for (int jj = 0; jj < NN; jj++) {
        float d = __fmul_rn(S[jj], x1[0]);
#pragma unroll
        for (int ii = 1; ii < NN; ii++) d = fmaf(S[ii * NN + jj], x1[ii], d);
        o2b[jj * INF + f] = __fadd_rn(x2[jj], d);
    }
}

static float* symaddr(const void* sym) {
    void* p = nullptr;
    cudaGetSymbolAddress(&p, sym);
    return (float*)p;
}

extern "C" void kernel_launch(void* const* d_in, const int* in_sizes, int n_in,
                              void* d_out, int out_size)
{
    const float* feat1  = (const float*)d_in[0];
    const float* feat2  = (const float*)d_in[1];
    const float* adj    = (const float*)d_in[2];
    const float* a_fc_w = (const float*)d_in[3];
    const float* a_fc_b = (const float*)d_in[4];
    const float* u_fc_w = (const float*)d_in[5];
    const float* u_fc_b = (const float*)d_in[6];
    const float* aff_A  = (const float*)d_in[7];

    float* out   = (float*)d_out;
    float* s_out = out;
    float* out1  = out + (size_t)BATCH * NN * NN;
    float* out2  = out1 + (size_t)BATCH * NN * INF;

    float* Wp = symaddr(g_Wpack);
    float* bp = symaddr(g_bpack);
    float* Y1 = symaddr(g_Y1);
    float* Y2 = symaddr(g_Y2);
    float* e1 = symaddr(g_e1);
    float* e2 = symaddr(g_e2);
    float* M1 = symaddr(g_M1);

    pack_w_kernel<<<(INF * OUTF + 255) / 256, 256>>>(a_fc_w, a_fc_b, u_fc_w, u_fc_b);

    // Y GEMMs split into M-halves so the ncu capture slot lands on sgemm.
    const int MH = MROWS / 2;
    dim3 gh(WN / 64, MH / 128);
    sgemm_kernel<<<gh, 256>>>(feat1,                    Wp, Y1,                   INF, WN, bp, 1);
    sgemm_kernel<<<gh, 256>>>(feat1 + (size_t)MH * INF, Wp, Y1 + (size_t)MH * WN, INF, WN, bp, 1);
    sgemm_kernel<<<gh, 256>>>(feat2,                    Wp, Y2,                   INF, WN, bp, 1);
    sgemm_kernel<<<gh, 256>>>(feat2 + (size_t)MH * INF, Wp, Y2 + (size_t)MH * WN, INF, WN, bp, 1);

    gconv_kernel<<<BATCH, 256>>>(adj, Y1, e1);
    gconv_kernel<<<BATCH, 256>>>(adj, Y2, e2);

    dim3 g2(OUTF / 64, MROWS / 128);
    sgemm_kernel<<<g2, 256>>>(e1, aff_A, M1, OUTF, OUTF, nullptr, 0);

    affinity_kernel<<<BATCH, 256>>>(M1, e2, s_out);

    dim3 g3(INF / 256, BATCH);
    fuse_kernel<<<g3, 256>>>(feat1, feat2, s_out, out1, out2);
}

// round 15
// speedup vs baseline: 1.1606x; 1.0271x over previous
#include <cuda_runtime.h>
#include <cstdint>
#include <cstddef>

#define BATCH 2048
#define NN    14
#define INF   2048
#define OUTF  1024
#define MROWS (BATCH * NN)
#define WN    (2 * OUTF)

// CPU (MXCSR FTZ) emulation: nonnegative tiny values below FLT_MIN -> 0.
__device__ __forceinline__ float ftzf(float x) {
    return (x < 1.17549435e-38f) ? 0.f : x;
}

// Packed fp32 FMA (Blackwell f32x2). Each lane is an independent IEEE fp32
// fma.rn -> bitwise identical to two scalar fmaf chains.
__device__ __forceinline__ void ffma2(unsigned long long& d,
                                      unsigned long long a,
                                      unsigned long long b) {
    asm("fma.rn.f32x2 %0, %1, %2, %0;" : "+l"(d) : "l"(a), "l"(b));
}
__device__ __forceinline__ unsigned long long dup2(float x) {
    unsigned long long r;
    asm("mov.b64 %0, {%1, %1};" : "=l"(r) : "r"(__float_as_uint(x)));
    return r;
}
__device__ __forceinline__ float lo32(unsigned long long v) {
    return __uint_as_float((unsigned)(v & 0xffffffffull));
}
__device__ __forceinline__ float hi32(unsigned long long v) {
    return __uint_as_float((unsigned)(v >> 32));
}

typedef unsigned long long u64;

// One kk step: 8 A-row broadcasts (dup2, ALU pipe) x 4 B column-pairs
// (direct packed u64 from Bs) -> 32 FFMA2 into acc2[8][4].
__device__ __forceinline__ void compute_kk(u64 (&acc2)[8][4],
                                           float4 aLo, float4 aHi,
                                           ulonglong2 bA, ulonglong2 bB)
{
    u64 bp[4] = { bA.x, bA.y, bB.x, bB.y };
    u64 ap[8] = { dup2(aLo.x), dup2(aLo.y), dup2(aLo.z), dup2(aLo.w),
                  dup2(aHi.x), dup2(aHi.y), dup2(aHi.z), dup2(aHi.w) };
#pragma unroll
    for (int i = 0; i < 8; i++)
#pragma unroll
        for (int j = 0; j < 4; j++)
            ffma2(acc2[i][j], ap[i], bp[j]);
}

__device__ float g_Wpack[INF * WN];
__device__ float g_bpack[WN];
__device__ float g_Y1[MROWS * WN];
__device__ float g_Y2[MROWS * WN];
__device__ float g_e1[MROWS * OUTF];
__device__ float g_e2[MROWS * OUTF];
__device__ float g_M1[MROWS * OUTF];

__global__ void pack_w_kernel(const float* __restrict__ aw, const float* __restrict__ ab,
                              const float* __restrict__ uw, const float* __restrict__ ub)
{
    int idx = blockIdx.x * blockDim.x + threadIdx.x;
    if (idx < INF * OUTF) {
        int k = idx >> 10, n = idx & 1023;
        g_Wpack[k * WN + n]        = aw[idx];
        g_Wpack[k * WN + OUTF + n] = uw[idx];
    }
    if (idx < OUTF) { g_bpack[idx] = ab[idx]; g_bpack[OUTF + idx] = ub[idx]; }
}

// fp32 SGEMM, sequential-k accumulation per output element (bitwise equal to
// an ascending-k fmaf chain). f32x2 N-packed (R11 shape) with an EXPLICIT
// kk-level software pipeline: unroll-by-2, two operand register sets, kk+1's
// LDS loads issued before kk's FFMA2 block so every load has a 32-FFMA2
// latency shadow. 128x128 tile, K-tile 16, 256 threads, 8x8/thread.
__global__ __launch_bounds__(256, 2)
void sgemm_kernel(const float* __restrict__ A, const float* __restrict__ B,
                  float* __restrict__ C, int K, int N,
                  const float* __restrict__ bias, int do_relu)
{
    __shared__ __align__(16) float As[2][16][132];   // [k][row]
    __shared__ __align__(16) float Bs[2][16][128];   // [k][col]

    const int tid = threadIdx.x, bm = blockIdx.y, bn = blockIdx.x;
    const float* Ab = A + (size_t)bm * 128 * K;
    const float* Bb = B + (size_t)bn * 128;

    const int arow = tid >> 2, acol = (tid & 3) * 4;
    const int brow = tid >> 5, bcol = (tid & 31) * 4;
    const int tx = tid & 15, ty = tid >> 4;

    // acc2[i][jp]: row i (0..3 -> ty*4+i, 4..7 -> 64+ty*4+i-4),
    // jp: 0 -> cols tx*4+0(lo),+1(hi); 1 -> +2,+3; 2 -> 64+tx*4+0,+1; 3 -> +2,+3
    u64 acc2[8][4];
#pragma unroll
    for (int i = 0; i < 8; i++)
#pragma unroll
        for (int j = 0; j < 4; j++) acc2[i][j] = 0ull;

    const int nk = K >> 4;

    // prologue: tile 0
    {
        float4 a0 = *(const float4*)(Ab + (size_t)arow * K + acol);
        float4 a1 = *(const float4*)(Ab + (size_t)(arow + 64) * K + acol);
        float4 b0 = *(const float4*)(Bb + (size_t)brow * N + bcol);
        float4 b1 = *(const float4*)(Bb + (size_t)(brow + 8) * N + bcol);
        As[0][acol+0][arow] = a0.x; As[0][acol+1][arow] = a0.y;
        As[0][acol+2][arow] = a0.z; As[0][acol+3][arow] = a0.w;
        As[0][acol+0][arow+64] = a1.x; As[0][acol+1][arow+64] = a1.y;
        As[0][acol+2][arow+64] = a1.z; As[0][acol+3][arow+64] = a1.w;
        *(float4*)&Bs[0][brow][bcol]     = b0;
        *(float4*)&Bs[0][brow + 8][bcol] = b1;
    }
    __syncthreads();

    for (int kt = 0; kt < nk; kt++) {
        const int cur = kt & 1, nxt = cur ^ 1;
        float4 na0, na1, nb0, nb1;
        const bool has_next = (kt + 1 < nk);
        if (has_next) {
            const float* Ap = Ab + (size_t)(kt + 1) * 16;
            const float* Bp = Bb + (size_t)(kt + 1) * 16 * N;
            na0 = *(const float4*)(Ap + (size_t)arow * K + acol);
            na1 = *(const float4*)(Ap + (size_t)(arow + 64) * K + acol);
            nb0 = *(const float4*)(Bp + (size_t)brow * N + bcol);
            nb1 = *(const float4*)(Bp + (size_t)(brow + 8) * N + bcol);
        }

        // operand set 0 primed with kk=0
        float4 aLo0 = *(const float4*)&As[cur][0][ty * 4];
        float4 aHi0 = *(const float4*)&As[cur][0][64 + ty * 4];
        ulonglong2 bA0 = *(const ulonglong2*)&Bs[cur][0][tx * 4];
        ulonglong2 bB0 = *(const ulonglong2*)&Bs[cur][0][64 + tx * 4];

#pragma unroll
        for (int kk = 0; kk < 16; kk += 2) {
            // load kk+1 into set 1 BEFORE computing kk (latency shadow)
            float4 aLo1 = *(const float4*)&As[cur][kk + 1][ty * 4];
            float4 aHi1 = *(const float4*)&As[cur][kk + 1][64 + ty * 4];
            ulonglong2 bA1 = *(const ulonglong2*)&Bs[cur][kk + 1][tx * 4];
            ulonglong2 bB1 = *(const ulonglong2*)&Bs[cur][kk + 1][64 + tx * 4];

            compute_kk(acc2, aLo0, aHi0, bA0, bB0);

            if (kk + 2 < 16) {
                aLo0 = *(const float4*)&As[cur][kk + 2][ty * 4];
                aHi0 = *(const float4*)&As[cur][kk + 2][64 + ty * 4];
                bA0 = *(const ulonglong2*)&Bs[cur][kk + 2][tx * 4];
                bB0 = *(const ulonglong2*)&Bs[cur][kk + 2][64 + tx * 4];
            }

            compute_kk(acc2, aLo1, aHi1, bA1, bB1);
        }

        if (has_next) {
            As[nxt][acol+0][arow] = na0.x; As[nxt][acol+1][arow] = na0.y;
            As[nxt][acol+2][arow] = na0.z; As[nxt][acol+3][arow] = na0.w;
            As[nxt][acol+0][arow+64] = na1.x; As[nxt][acol+1][arow+64] = na1.y;
            As[nxt][acol+2][arow+64] = na1.z; As[nxt][acol+3][arow+64] = na1.w;
            *(float4*)&Bs[nxt][brow][bcol]     = nb0;
            *(float4*)&Bs[nxt][brow + 8][bcol] = nb1;
            __syncthreads();
        }
    }

    const int row0 = bm * 128, col0 = bn * 128;
    float bb[8];
    if (bias) {
#pragma unroll
        for (int j = 0; j < 4; j++) {
            bb[j]     = bias[col0 + tx * 4 + j];
            bb[4 + j] = bias[col0 + 64 + tx * 4 + j];
        }
    } else {
#pragma unroll
        for (int j = 0; j < 8; j++) bb[j] = 0.f;
    }
#pragma unroll
    for (int i = 0; i < 8; i++) {
        const int m = (i < 4) ? (ty * 4 + i) : (64 + ty * 4 + (i - 4));
        float* Crow = C + (size_t)(row0 + m) * N + col0;
        float v[8];
        v[0] = lo32(acc2[i][0]); v[1] = hi32(acc2[i][0]);
        v[2] = lo32(acc2[i][1]); v[3] = hi32(acc2[i][1]);
        v[4] = lo32(acc2[i][2]); v[5] = hi32(acc2[i][2]);
        v[6] = lo32(acc2[i][3]); v[7] = hi32(acc2[i][3]);
#pragma unroll
        for (int j = 0; j < 8; j++) {
            float x = __fadd_rn(v[j], bb[j]);
            v[j] = do_relu ? fmaxf(x, 0.f) : x;
        }
        *(float4*)(Crow + tx * 4)      = make_float4(v[0], v[1], v[2], v[3]);
        *(float4*)(Crow + 64 + tx * 4) = make_float4(v[4], v[5], v[6], v[7]);
    }
}

// Gconv: e = bmm(Anorm, AX) + UX (dot from zero, then elementwise add).
__global__ void gconv_kernel(const float* __restrict__ adj, const float* __restrict__ Y,
                             float* __restrict__ e)
{
    const int b = blockIdx.x, tid = threadIdx.x;
    __shared__ float sA[NN * NN];
    __shared__ float cs[NN];
    __shared__ float An[NN][NN + 2];

    if (tid < NN * NN) sA[tid] = adj[(size_t)b * NN * NN + tid];
    __syncthreads();
    if (tid < NN) {
        float s = 0.f;
#pragma unroll
        for (int i = 0; i < NN; i++) s = __fadd_rn(s, sA[i * NN + tid]);
        cs[tid] = fmaxf(s, 1e-12f);
    }
    __syncthreads();
    if (tid < NN * NN) {
        int i = tid / NN, j = tid - i * NN;
        An[i][j] = __fdiv_rn(sA[tid], cs[j]);
    }
    __syncthreads();

    const float* Yb = Y + (size_t)b * NN * WN;
    float* eb = e + (size_t)b * NN * OUTF;
    for (int f = tid; f < OUTF; f += blockDim.x) {
        float ax[NN], ux[NN];
#pragma unroll
        for (int j = 0; j < NN; j++) {
            ax[j] = Yb[j * WN + f];
            ux[j] = Yb[j * WN + OUTF + f];
        }
#pragma unroll
        for (int i = 0; i < NN; i++) {
            float d = __fmul_rn(An[i][0], ax[0]);
#pragma unroll
            for (int j = 1; j < NN; j++) d = fmaf(An[i][j], ax[j], d);
            eb[i * OUTF + f] = __fadd_rn(d, ux[i]);
        }
    }
}

// Affinity gram (sequential fp32) + softmax(200*s) + 20 Sinkhorn iters with
// FTZ emulation at every tiny-value production site.
__global__ void affinity_kernel(const float* __restrict__ Mx, const float* __restrict__ E2,
                                float* __restrict__ s_out)
{
    const int b = blockIdx.x, tid = threadIdx.x;
    __shared__ float sM[NN][129];
    __shared__ float sE[NN][129];
    __shared__ float S[NN][NN + 1];

    const float* Mb = Mx + (size_t)b * NN * OUTF;
    const float* Eb = E2 + (size_t)b * NN * OUTF;
    const int i = tid / NN, j = tid - i * NN;
    float acc = 0.f;

    for (int d0 = 0; d0 < OUTF; d0 += 128) {
        for (int t = tid; t < NN * 128; t += 256) {
            int r = t >> 7, c = t & 127;
            sM[r][c] = Mb[r * OUTF + d0 + c];
            sE[r][c] = Eb[r * OUTF + d0 + c];
        }
        __syncthreads();
        if (tid < NN * NN) {
#pragma unroll 8
            for (int c = 0; c < 128; c++)
                acc = fmaf(sM[i][c], sE[j][c], acc);
        }
        __syncthreads();
    }
    if (tid < NN * NN) S[i][j] = acc;
    __syncthreads();

    if (tid < NN) {
        float t[NN], m = -__int_as_float(0x7f800000);
#pragma unroll
        for (int jj = 0; jj < NN; jj++) {
            t[jj] = __fmul_rn(200.f, S[tid][jj]);
            m = fmaxf(m, t[jj]);
        }
        float p[NN], sum = 0.f;
#pragma unroll
        for (int jj = 0; jj < NN; jj++) {
            p[jj] = ftzf(expf(__fadd_rn(t[jj], -m)));
            sum = __fadd_rn(sum, p[jj]);
        }
#pragma unroll
        for (int jj = 0; jj < NN; jj++)
            S[tid][jj] = ftzf(__fdiv_rn(p[jj], sum));
    }
    __syncthreads();

    for (int it = 0; it < 20; it++) {
        if ((it & 1) == 0) {
            if (tid < NN) {
                float sum = 0.f;
#pragma unroll
                for (int jj = 0; jj < NN; jj++) sum = __fadd_rn(sum, S[tid][jj]);
                sum = __fadd_rn(sum, 1e-10f);
#pragma unroll
                for (int jj = 0; jj < NN; jj++)
                    S[tid][jj] = ftzf(__fdiv_rn(S[tid][jj], sum));
            }
        } else {
            if (tid < NN) {
                float sum = 0.f;
#pragma unroll
                for (int ii = 0; ii < NN; ii++) sum = __fadd_rn(sum, S[ii][tid]);
                sum = __fadd_rn(sum, 1e-10f);
#pragma unroll
                for (int ii = 0; ii < NN; ii++)
                    S[ii][tid] = ftzf(__fdiv_rn(S[ii][tid], sum));
            }
        }
        __syncthreads();
    }
    if (tid < NN * NN) s_out[(size_t)b * NN * NN + tid] = S[i][j];
}

// Fusion: dot from zero over the contraction index, then add feat.
__global__ void fuse_kernel(const float* __restrict__ f1, const float* __restrict__ f2,
                            const float* __restrict__ s,
                            float* __restrict__ o1, float* __restrict__ o2)
{
    const int b = blockIdx.y;
    const int f = blockIdx.x * blockDim.x + threadIdx.x;
    __shared__ float S[NN * NN];
    if (threadIdx.x < NN * NN) S[threadIdx.x] = s[(size_t)b * NN * NN + threadIdx.x];
    __syncthreads();

    const float* f1b = f1 + (size_t)b * NN * INF;
    const float* f2b = f2 + (size_t)b * NN * INF;
    float* o1b = o1 + (size_t)b * NN * INF;
    float* o2b = o2 + (size_t)b * NN * INF;

    float x1[NN], x2[NN];
#pragma unroll
    for (int r = 0; r < NN; r++) { x1[r] = f1b[r * INF + f]; x2[r] = f2b[r * INF + f]; }
#pragma unroll
    for (int i = 0; i < NN; i++) {
        float d = __fmul_rn(S[i * NN], x2[0]);
#pragma unroll
        for (int jj = 1; jj < NN; jj++) d = fmaf(S[i * NN + jj], x2[jj], d);
        o1b[i * INF + f] = __fadd_rn(x1[i], d);
    }
#pragma unroll
    for (int jj = 0; jj < NN; jj++) {
        float d = __fmul_rn(S[jj], x1[0]);
#pragma unroll
        for (int ii = 1; ii < NN; ii++) d = fmaf(S[ii * NN + jj], x1[ii], d);
        o2b[jj * INF + f] = __fadd_rn(x2[jj], d);
    }
}

static float* symaddr(const void* sym) {
    void* p = nullptr;
    cudaGetSymbolAddress(&p, sym);
    return (float*)p;
}

extern "C" void kernel_launch(void* const* d_in, const int* in_sizes, int n_in,
                              void* d_out, int out_size)
{
    const float* feat1  = (const float*)d_in[0];
    const float* feat2  = (const float*)d_in[1];
    const float* adj    = (const float*)d_in[2];
    const float* a_fc_w = (const float*)d_in[3];
    const float* a_fc_b = (const float*)d_in[4];
    const float* u_fc_w = (const float*)d_in[5];
    const float* u_fc_b = (const float*)d_in[6];
    const float* aff_A  = (const float*)d_in[7];

    float* out   = (float*)d_out;
    float* s_out = out;
    float* out1  = out + (size_t)BATCH * NN * NN;
    float* out2  = out1 + (size_t)BATCH * NN * INF;

    float* Wp = symaddr(g_Wpack);
    float* bp = symaddr(g_bpack);
    float* Y1 = symaddr(g_Y1);
    float* Y2 = symaddr(g_Y2);
    float* e1 = symaddr(g_e1);
    float* e2 = symaddr(g_e2);
    float* M1 = symaddr(g_M1);

    pack_w_kernel<<<(INF * OUTF + 255) / 256, 256>>>(a_fc_w, a_fc_b, u_fc_w, u_fc_b);

    // Y GEMMs split into M-halves so the ncu capture slot lands on sgemm.
    const int MH = MROWS / 2;
    dim3 gh(WN / 128, MH / 128);
    sgemm_kernel<<<gh, 256>>>(feat1,                    Wp, Y1,                   INF, WN, bp, 1);
    sgemm_kernel<<<gh, 256>>>(feat1 + (size_t)MH * INF, Wp, Y1 + (size_t)MH * WN, INF, WN, bp, 1);
    sgemm_kernel<<<gh, 256>>>(feat2,                    Wp, Y2,                   INF, WN, bp, 1);
    sgemm_kernel<<<gh, 256>>>(feat2 + (size_t)MH * INF, Wp, Y2 + (size_t)MH * WN, INF, WN, bp, 1);

    gconv_kernel<<<BATCH, 256>>>(adj, Y1, e1);
    gconv_kernel<<<BATCH, 256>>>(adj, Y2, e2);

    dim3 g2(OUTF / 128, MROWS / 128);
    sgemm_kernel<<<g2, 256>>>(e1, aff_A, M1, OUTF, OUTF, nullptr, 0);

    affinity_kernel<<<BATCH, 256>>>(M1, e2, s_out);

    dim3 g3(INF / 256, BATCH);
    fuse_kernel<<<g3, 256>>>(feat1, feat2, s_out, out1, out2);
}

// round 16
// speedup vs baseline: 1.2019x; 1.0355x over previous
#include <cuda_runtime.h>
#include <cstdint>
#include <cstddef>

#define BATCH 2048
#define NN    14
#define INF   2048
#define OUTF  1024
#define MROWS (BATCH * NN)
#define WN    (2 * OUTF)

// CPU (MXCSR FTZ) emulation: nonnegative tiny values below FLT_MIN -> 0.
__device__ __forceinline__ float ftzf(float x) {
    return (x < 1.17549435e-38f) ? 0.f : x;
}

// Packed fp32 FMA (Blackwell f32x2). Each lane is an independent IEEE fp32
// fma.rn -> bitwise identical to two scalar fmaf chains.
__device__ __forceinline__ void ffma2(unsigned long long& d,
                                      unsigned long long a,
                                      unsigned long long b) {
    asm("fma.rn.f32x2 %0, %1, %2, %0;" : "+l"(d) : "l"(a), "l"(b));
}
__device__ __forceinline__ unsigned long long dup2(float x) {
    unsigned long long r;
    asm("mov.b64 %0, {%1, %1};" : "=l"(r) : "r"(__float_as_uint(x)));
    return r;
}
__device__ __forceinline__ float lo32(unsigned long long v) {
    return __uint_as_float((unsigned)(v & 0xffffffffull));
}
__device__ __forceinline__ float hi32(unsigned long long v) {
    return __uint_as_float((unsigned)(v >> 32));
}

typedef unsigned long long u64;

__device__ float g_Wpack[INF * WN];
__device__ float g_bpack[WN];
__device__ float g_Y1[MROWS * WN];
__device__ float g_Y2[MROWS * WN];
__device__ float g_e1[MROWS * OUTF];
__device__ float g_e2[MROWS * OUTF];
__device__ float g_M1[MROWS * OUTF];

__global__ void pack_w_kernel(const float* __restrict__ aw, const float* __restrict__ ab,
                              const float* __restrict__ uw, const float* __restrict__ ub)
{
    int idx = blockIdx.x * blockDim.x + threadIdx.x;
    if (idx < INF * OUTF) {
        int k = idx >> 10, n = idx & 1023;
        g_Wpack[k * WN + n]        = aw[idx];
        g_Wpack[k * WN + OUTF + n] = uw[idx];
    }
    if (idx < OUTF) { g_bpack[idx] = ab[idx]; g_bpack[OUTF + idx] = ub[idx]; }
}

// fp32 SGEMM, sequential-k accumulation per output element (bitwise equal to
// an ascending-k fmaf chain). f32x2 N-packed (R11 optimum): u64 accumulator
// holds columns (j, j+1) of one row; B pairs load directly from plain Bs as
// aligned u64 pairs; A broadcast via dup2 (ALU pipe). blockIdx.z selects the
// (A1,C1)/(A2,C2) pair so two GEMMs share one launch (tail-wave overlap).
// 128x128 tile, K-tile 16, 256 threads, 8x8 outputs/thread, double-buffered.
__global__ __launch_bounds__(256, 2)
void sgemm_kernel(const float* __restrict__ A1, const float* __restrict__ A2,
                  const float* __restrict__ B,
                  float* __restrict__ C1, float* __restrict__ C2,
                  int K, int N,
                  const float* __restrict__ bias, int do_relu)
{
    __shared__ __align__(16) float As[2][16][132];   // [k][row]
    __shared__ __align__(16) float Bs[2][16][128];   // [k][col]

    const int tid = threadIdx.x, bm = blockIdx.y, bn = blockIdx.x;
    const float* A = (blockIdx.z == 0) ? A1 : A2;
    float*       C = (blockIdx.z == 0) ? C1 : C2;
    const float* Ab = A + (size_t)bm * 128 * K;
    const float* Bb = B + (size_t)bn * 128;

    const int arow = tid >> 2, acol = (tid & 3) * 4;
    const int brow = tid >> 5, bcol = (tid & 31) * 4;
    const int tx = tid & 15, ty = tid >> 4;

    u64 acc2[8][4];
#pragma unroll
    for (int i = 0; i < 8; i++)
#pragma unroll
        for (int j = 0; j < 4; j++) acc2[i][j] = 0ull;

    const int nk = K >> 4;

    // prologue: tile 0
    {
        float4 a0 = *(const float4*)(Ab + (size_t)arow * K + acol);
        float4 a1 = *(const float4*)(Ab + (size_t)(arow + 64) * K + acol);
        float4 b0 = *(const float4*)(Bb + (size_t)brow * N + bcol);
        float4 b1 = *(const float4*)(Bb + (size_t)(brow + 8) * N + bcol);
        As[0][acol+0][arow] = a0.x; As[0][acol+1][arow] = a0.y;
        As[0][acol+2][arow] = a0.z; As[0][acol+3][arow] = a0.w;
        As[0][acol+0][arow+64] = a1.x; As[0][acol+1][arow+64] = a1.y;
        As[0][acol+2][arow+64] = a1.z; As[0][acol+3][arow+64] = a1.w;
        *(float4*)&Bs[0][brow][bcol]     = b0;
        *(float4*)&Bs[0][brow + 8][bcol] = b1;
    }
    __syncthreads();

    for (int kt = 0; kt < nk; kt++) {
        const int cur = kt & 1, nxt = cur ^ 1;
        float4 na0, na1, nb0, nb1;
        const bool has_next = (kt + 1 < nk);
        if (has_next) {
            const float* Ap = Ab + (size_t)(kt + 1) * 16;
            const float* Bp = Bb + (size_t)(kt + 1) * 16 * N;
            na0 = *(const float4*)(Ap + (size_t)arow * K + acol);
            na1 = *(const float4*)(Ap + (size_t)(arow + 64) * K + acol);
            nb0 = *(const float4*)(Bp + (size_t)brow * N + bcol);
            nb1 = *(const float4*)(Bp + (size_t)(brow + 8) * N + bcol);
        }
#pragma unroll
        for (int kk = 0; kk < 16; kk++) {
            float4 aLo = *(const float4*)&As[cur][kk][ty * 4];
            float4 aHi = *(const float4*)&As[cur][kk][64 + ty * 4];
            ulonglong2 bA = *(const ulonglong2*)&Bs[cur][kk][tx * 4];
            ulonglong2 bB = *(const ulonglong2*)&Bs[cur][kk][64 + tx * 4];
            u64 bp[4] = { bA.x, bA.y, bB.x, bB.y };
            u64 ap[8] = { dup2(aLo.x), dup2(aLo.y), dup2(aLo.z), dup2(aLo.w),
                          dup2(aHi.x), dup2(aHi.y), dup2(aHi.z), dup2(aHi.w) };
#pragma unroll
            for (int i = 0; i < 8; i++)
#pragma unroll
                for (int j = 0; j < 4; j++)
                    ffma2(acc2[i][j], ap[i], bp[j]);
        }
        if (has_next) {
            As[nxt][acol+0][arow] = na0.x; As[nxt][acol+1][arow] = na0.y;
            As[nxt][acol+2][arow] = na0.z; As[nxt][acol+3][arow] = na0.w;
            As[nxt][acol+0][arow+64] = na1.x; As[nxt][acol+1][arow+64] = na1.y;
            As[nxt][acol+2][arow+64] = na1.z; As[nxt][acol+3][arow+64] = na1.w;
            *(float4*)&Bs[nxt][brow][bcol]     = nb0;
            *(float4*)&Bs[nxt][brow + 8][bcol] = nb1;
            __syncthreads();
        }
    }

    const int row0 = bm * 128, col0 = bn * 128;
    float bb[8];
    if (bias) {
#pragma unroll
        for (int j = 0; j < 4; j++) {
            bb[j]     = bias[col0 + tx * 4 + j];
            bb[4 + j] = bias[col0 + 64 + tx * 4 + j];
        }
    } else {
#pragma unroll
        for (int j = 0; j < 8; j++) bb[j] = 0.f;
    }
#pragma unroll
    for (int i = 0; i < 8; i++) {
        const int m = (i < 4) ? (ty * 4 + i) : (64 + ty * 4 + (i - 4));
        float* Crow = C + (size_t)(row0 + m) * N + col0;
        float v[8];
        v[0] = lo32(acc2[i][0]); v[1] = hi32(acc2[i][0]);
        v[2] = lo32(acc2[i][1]); v[3] = hi32(acc2[i][1]);
        v[4] = lo32(acc2[i][2]); v[5] = hi32(acc2[i][2]);
        v[6] = lo32(acc2[i][3]); v[7] = hi32(acc2[i][3]);
#pragma unroll
        for (int j = 0; j < 8; j++) {
            float x = __fadd_rn(v[j], bb[j]);
            v[j] = do_relu ? fmaxf(x, 0.f) : x;
        }
        *(float4*)(Crow + tx * 4)      = make_float4(v[0], v[1], v[2], v[3]);
        *(float4*)(Crow + 64 + tx * 4) = make_float4(v[4], v[5], v[6], v[7]);
    }
}

// Gconv: e = bmm(Anorm, AX) + UX (dot from zero, then elementwise add).
// Reworked for occupancy: grid (BATCH, 4, 2); each thread handles exactly ONE
// feature column (f = blockIdx.y*256 + tid), z selects (Y1,e1)/(Y2,e2).
// Identical per-element arithmetic and order as before -> bit-exact.
__global__ void gconv_kernel(const float* __restrict__ adj,
                             const float* __restrict__ Y1, const float* __restrict__ Y2,
                             float* __restrict__ e1, float* __restrict__ e2)
{
    const int b = blockIdx.x, tid = threadIdx.x;
    const float* Y = (blockIdx.z == 0) ? Y1 : Y2;
    float*       e = (blockIdx.z == 0) ? e1 : e2;

    __shared__ float sA[NN * NN];
    __shared__ float cs[NN];
    __shared__ float An[NN][NN + 2];

    if (tid < NN * NN) sA[tid] = adj[(size_t)b * NN * NN + tid];
    __syncthreads();
    if (tid < NN) {
        float s = 0.f;
#pragma unroll
        for (int i = 0; i < NN; i++) s = __fadd_rn(s, sA[i * NN + tid]);
        cs[tid] = fmaxf(s, 1e-12f);
    }
    __syncthreads();
    if (tid < NN * NN) {
        int i = tid / NN, j = tid - i * NN;
        An[i][j] = __fdiv_rn(sA[tid], cs[j]);
    }
    __syncthreads();

    const int f = blockIdx.y * 256 + tid;   // 0..1023
    const float* Yb = Y + (size_t)b * NN * WN;
    float* eb = e + (size_t)b * NN * OUTF;

    float ax[NN], ux[NN];
#pragma unroll
    for (int j = 0; j < NN; j++) {
        ax[j] = Yb[j * WN + f];
        ux[j] = Yb[j * WN + OUTF + f];
    }
#pragma unroll
    for (int i = 0; i < NN; i++) {
        float d = __fmul_rn(An[i][0], ax[0]);
#pragma unroll
        for (int j = 1; j < NN; j++) d = fmaf(An[i][j], ax[j], d);
        eb[i * OUTF + f] = __fadd_rn(d, ux[i]);
    }
}

// Affinity gram (sequential fp32) + softmax(200*s) + 20 Sinkhorn iters with
// FTZ emulation at every tiny-value production site.
__global__ void affinity_kernel(const float* __restrict__ Mx, const float* __restrict__ E2,
                                float* __restrict__ s_out)
{
    const int b = blockIdx.x, tid = threadIdx.x;
    __shared__ float sM[NN][129];
    __shared__ float sE[NN][129];
    __shared__ float S[NN][NN + 1];

    const float* Mb = Mx + (size_t)b * NN * OUTF;
    const float* Eb = E2 + (size_t)b * NN * OUTF;
    const int i = tid / NN, j = tid - i * NN;
    float acc = 0.f;

    for (int d0 = 0; d0 < OUTF; d0 += 128) {
        for (int t = tid; t < NN * 128; t += 256) {
            int r = t >> 7, c = t & 127;
            sM[r][c] = Mb[r * OUTF + d0 + c];
            sE[r][c] = Eb[r * OUTF + d0 + c];
        }
        __syncthreads();
        if (tid < NN * NN) {
#pragma unroll 8
            for (int c = 0; c < 128; c++)
                acc = fmaf(sM[i][c], sE[j][c], acc);
        }
        __syncthreads();
    }
    if (tid < NN * NN) S[i][j] = acc;
    __syncthreads();

    if (tid < NN) {
        float t[NN], m = -__int_as_float(0x7f800000);
#pragma unroll
        for (int jj = 0; jj < NN; jj++) {
            t[jj] = __fmul_rn(200.f, S[tid][jj]);
            m = fmaxf(m, t[jj]);
        }
        float p[NN], sum = 0.f;
#pragma unroll
        for (int jj = 0; jj < NN; jj++) {
            p[jj] = ftzf(expf(__fadd_rn(t[jj], -m)));
            sum = __fadd_rn(sum, p[jj]);
        }
#pragma unroll
        for (int jj = 0; jj < NN; jj++)
            S[tid][jj] = ftzf(__fdiv_rn(p[jj], sum));
    }
    __syncthreads();

    for (int it = 0; it < 20; it++) {
        if ((it & 1) == 0) {
            if (tid < NN) {
                float sum = 0.f;
#pragma unroll
                for (int jj = 0; jj < NN; jj++) sum = __fadd_rn(sum, S[tid][jj]);
                sum = __fadd_rn(sum, 1e-10f);
#pragma unroll
                for (int jj = 0; jj < NN; jj++)
                    S[tid][jj] = ftzf(__fdiv_rn(S[tid][jj], sum));
            }
        } else {
            if (tid < NN) {
                float sum = 0.f;
#pragma unroll
                for (int ii = 0; ii < NN; ii++) sum = __fadd_rn(sum, S[ii][tid]);
                sum = __fadd_rn(sum, 1e-10f);
#pragma unroll
                for (int ii = 0; ii < NN; ii++)
                    S[ii][tid] = ftzf(__fdiv_rn(S[ii][tid], sum));
            }
        }
        __syncthreads();
    }
    if (tid < NN * NN) s_out[(size_t)b * NN * NN + tid] = S[i][j];
}

// Fusion: dot from zero over the contraction index, then add feat.
__global__ void fuse_kernel(const float* __restrict__ f1, const float* __restrict__ f2,
                            const float* __restrict__ s,
                            float* __restrict__ o1, float* __restrict__ o2)
{
    const int b = blockIdx.y;
    const int f = blockIdx.x * blockDim.x + threadIdx.x;
    __shared__ float S[NN * NN];
    if (threadIdx.x < NN * NN) S[threadIdx.x] = s[(size_t)b * NN * NN + threadIdx.x];
    __syncthreads();

    const float* f1b = f1 + (size_t)b * NN * INF;
    const float* f2b = f2 + (size_t)b * NN * INF;
    float* o1b = o1 + (size_t)b * NN * INF;
    float* o2b = o2 + (size_t)b * NN * INF;

    float x1[NN], x2[NN];
#pragma unroll
    for (int r = 0; r < NN; r++) { x1[r] = f1b[r * INF + f]; x2[r] = f2b[r * INF + f]; }
#pragma unroll
    for (int i = 0; i < NN; i++) {
        float d = __fmul_rn(S[i * NN], x2[0]);
#pragma unroll
        for (int jj = 1; jj < NN; jj++) d = fmaf(S[i * NN + jj], x2[jj], d);
        o1b[i * INF + f] = __fadd_rn(x1[i], d);
    }
#pragma unroll
    for (int jj = 0; jj < NN; jj++) {
        float d = __fmul_rn(S[jj], x1[0]);
#pragma unroll
        for (int ii = 1; ii < NN; ii++) d = fmaf(S[ii * NN + jj], x1[ii], d);
        o2b[jj * INF + f] = __fadd_rn(x2[jj], d);
    }
}

static float* symaddr(const void* sym) {
    void* p = nullptr;
    cudaGetSymbolAddress(&p, sym);
    return (float*)p;
}

extern "C" void kernel_launch(void* const* d_in, const int* in_sizes, int n_in,
                              void* d_out, int out_size)
{
    const float* feat1  = (const float*)d_in[0];
    const float* feat2  = (const float*)d_in[1];
    const float* adj    = (const float*)d_in[2];
    const float* a_fc_w = (const float*)d_in[3];
    const float* a_fc_b = (const float*)d_in[4];
    const float* u_fc_w = (const float*)d_in[5];
    const float* u_fc_b = (const float*)d_in[6];
    const float* aff_A  = (const float*)d_in[7];

    float* out   = (float*)d_out;
    float* s_out = out;
    float* out1  = out + (size_t)BATCH * NN * NN;
    float* out2  = out1 + (size_t)BATCH * NN * INF;

    float* Wp = symaddr(g_Wpack);
    float* bp = symaddr(g_bpack);
    float* Y1 = symaddr(g_Y1);
    float* Y2 = symaddr(g_Y2);
    float* e1 = symaddr(g_e1);
    float* e2 = symaddr(g_e2);
    float* M1 = symaddr(g_M1);

    pack_w_kernel<<<(INF * OUTF + 255) / 256, 256>>>(a_fc_w, a_fc_b, u_fc_w, u_fc_b);

    // Both Y GEMMs in ONE launch: grid.z selects (feat1->Y1) / (feat2->Y2).
    dim3 g1(WN / 128, MROWS / 128, 2);
    sgemm_kernel<<<g1, 256>>>(feat1, feat2, Wp, Y1, Y2, INF, WN, bp, 1);

    // Both gconvs in ONE launch: grid (batch, f-chunk, which-feat).
    dim3 gg(BATCH, OUTF / 256, 2);
    gconv_kernel<<<gg, 256>>>(adj, Y1, Y2, e1, e2);

    // M1 = e1 @ aff_A (single GEMM; z-dim of 1 -> picks the first pair).
    dim3 g2(OUTF / 128, MROWS / 128, 1);
    sgemm_kernel<<<g2, 256>>>(e1, e1, aff_A, M1, M1, OUTF, OUTF, nullptr, 0);

    affinity_kernel<<<BATCH, 256>>>(M1, e2, s_out);

    dim3 g3(INF / 256, BATCH);
    fuse_kernel<<<g3, 256>>>(feat1, feat2, s_out, out1, out2);
}

// round 17
// speedup vs baseline: 1.2293x; 1.0228x over previous
#include <cuda_runtime.h>
#include <cstdint>
#include <cstddef>

#define BATCH 2048
#define NN    14
#define INF   2048
#define OUTF  1024
#define MROWS (BATCH * NN)
#define WN    (2 * OUTF)

// CPU (MXCSR FTZ) emulation: nonnegative tiny values below FLT_MIN -> 0.
__device__ __forceinline__ float ftzf(float x) {
    return (x < 1.17549435e-38f) ? 0.f : x;
}

// Packed fp32 FMA (Blackwell f32x2). Each lane is an independent IEEE fp32
// fma.rn -> bitwise identical to two scalar fmaf chains.
__device__ __forceinline__ void ffma2(unsigned long long& d,
                                      unsigned long long a,
                                      unsigned long long b) {
    asm("fma.rn.f32x2 %0, %1, %2, %0;" : "+l"(d) : "l"(a), "l"(b));
}
__device__ __forceinline__ unsigned long long dup2(float x) {
    unsigned long long r;
    asm("mov.b64 %0, {%1, %1};" : "=l"(r) : "r"(__float_as_uint(x)));
    return r;
}
__device__ __forceinline__ float lo32(unsigned long long v) {
    return __uint_as_float((unsigned)(v & 0xffffffffull));
}
__device__ __forceinline__ float hi32(unsigned long long v) {
    return __uint_as_float((unsigned)(v >> 32));
}

typedef unsigned long long u64;

__device__ float g_Wpack[INF * WN];
__device__ float g_bpack[WN];
__device__ float g_Y1[MROWS * WN];
__device__ float g_Y2[MROWS * WN];
__device__ float g_e1[MROWS * OUTF];
__device__ float g_e2[MROWS * OUTF];
__device__ float g_M1[MROWS * OUTF];

__global__ void pack_w_kernel(const float* __restrict__ aw, const float* __restrict__ ab,
                              const float* __restrict__ uw, const float* __restrict__ ub)
{
    int idx = blockIdx.x * blockDim.x + threadIdx.x;
    if (idx < INF * OUTF) {
        int k = idx >> 10, n = idx & 1023;
        g_Wpack[k * WN + n]        = aw[idx];
        g_Wpack[k * WN + OUTF + n] = uw[idx];
    }
    if (idx < OUTF) { g_bpack[idx] = ab[idx]; g_bpack[OUTF + idx] = ub[idx]; }
}

// fp32 SGEMM, sequential-k accumulation per output element (bitwise equal to
// an ascending-k fmaf chain). f32x2 N-packed (R11 optimum): u64 accumulator
// holds columns (j, j+1) of one row; B pairs load directly from plain Bs as
// aligned u64 pairs; A broadcast via dup2 (ALU pipe).
// 128x128 tile, K-tile 16, 256 threads, 8x8 outputs/thread, double-buffered.
__global__ __launch_bounds__(256, 2)
void sgemm_kernel(const float* __restrict__ A, const float* __restrict__ B,
                  float* __restrict__ C, int K, int N,
                  const float* __restrict__ bias, int do_relu)
{
    __shared__ __align__(16) float As[2][16][132];   // [k][row]
    __shared__ __align__(16) float Bs[2][16][128];   // [k][col]

    const int tid = threadIdx.x, bm = blockIdx.y, bn = blockIdx.x;
    const float* Ab = A + (size_t)bm * 128 * K;
    const float* Bb = B + (size_t)bn * 128;

    const int arow = tid >> 2, acol = (tid & 3) * 4;
    const int brow = tid >> 5, bcol = (tid & 31) * 4;
    const int tx = tid & 15, ty = tid >> 4;

    u64 acc2[8][4];
#pragma unroll
    for (int i = 0; i < 8; i++)
#pragma unroll
        for (int j = 0; j < 4; j++) acc2[i][j] = 0ull;

    const int nk = K >> 4;

    // prologue: tile 0
    {
        float4 a0 = *(const float4*)(Ab + (size_t)arow * K + acol);
        float4 a1 = *(const float4*)(Ab + (size_t)(arow + 64) * K + acol);
        float4 b0 = *(const float4*)(Bb + (size_t)brow * N + bcol);
        float4 b1 = *(const float4*)(Bb + (size_t)(brow + 8) * N + bcol);
        As[0][acol+0][arow] = a0.x; As[0][acol+1][arow] = a0.y;
        As[0][acol+2][arow] = a0.z; As[0][acol+3][arow] = a0.w;
        As[0][acol+0][arow+64] = a1.x; As[0][acol+1][arow+64] = a1.y;
        As[0][acol+2][arow+64] = a1.z; As[0][acol+3][arow+64] = a1.w;
        *(float4*)&Bs[0][brow][bcol]     = b0;
        *(float4*)&Bs[0][brow + 8][bcol] = b1;
    }
    __syncthreads();

    for (int kt = 0; kt < nk; kt++) {
        const int cur = kt & 1, nxt = cur ^ 1;
        float4 na0, na1, nb0, nb1;
        const bool has_next = (kt + 1 < nk);
        if (has_next) {
            const float* Ap = Ab + (size_t)(kt + 1) * 16;
            const float* Bp = Bb + (size_t)(kt + 1) * 16 * N;
            na0 = *(const float4*)(Ap + (size_t)arow * K + acol);
            na1 = *(const float4*)(Ap + (size_t)(arow + 64) * K + acol);
            nb0 = *(const float4*)(Bp + (size_t)brow * N + bcol);
            nb1 = *(const float4*)(Bp + (size_t)(brow + 8) * N + bcol);
        }
#pragma unroll
        for (int kk = 0; kk < 16; kk++) {
            float4 aLo = *(const float4*)&As[cur][kk][ty * 4];
            float4 aHi = *(const float4*)&As[cur][kk][64 + ty * 4];
            ulonglong2 bA = *(const ulonglong2*)&Bs[cur][kk][tx * 4];
            ulonglong2 bB = *(const ulonglong2*)&Bs[cur][kk][64 + tx * 4];
            u64 bp[4] = { bA.x, bA.y, bB.x, bB.y };
            u64 ap[8] = { dup2(aLo.x), dup2(aLo.y), dup2(aLo.z), dup2(aLo.w),
                          dup2(aHi.x), dup2(aHi.y), dup2(aHi.z), dup2(aHi.w) };
#pragma unroll
            for (int i = 0; i < 8; i++)
#pragma unroll
                for (int j = 0; j < 4; j++)
                    ffma2(acc2[i][j], ap[i], bp[j]);
        }
        if (has_next) {
            As[nxt][acol+0][arow] = na0.x; As[nxt][acol+1][arow] = na0.y;
            As[nxt][acol+2][arow] = na0.z; As[nxt][acol+3][arow] = na0.w;
            As[nxt][acol+0][arow+64] = na1.x; As[nxt][acol+1][arow+64] = na1.y;
            As[nxt][acol+2][arow+64] = na1.z; As[nxt][acol+3][arow+64] = na1.w;
            *(float4*)&Bs[nxt][brow][bcol]     = nb0;
            *(float4*)&Bs[nxt][brow + 8][bcol] = nb1;
            __syncthreads();
        }
    }

    const int row0 = bm * 128, col0 = bn * 128;
    float bb[8];
    if (bias) {
#pragma unroll
        for (int j = 0; j < 4; j++) {
            bb[j]     = bias[col0 + tx * 4 + j];
            bb[4 + j] = bias[col0 + 64 + tx * 4 + j];
        }
    } else {
#pragma unroll
        for (int j = 0; j < 8; j++) bb[j] = 0.f;
    }
#pragma unroll
    for (int i = 0; i < 8; i++) {
        const int m = (i < 4) ? (ty * 4 + i) : (64 + ty * 4 + (i - 4));
        float* Crow = C + (size_t)(row0 + m) * N + col0;
        float v[8];
        v[0] = lo32(acc2[i][0]); v[1] = hi32(acc2[i][0]);
        v[2] = lo32(acc2[i][1]); v[3] = hi32(acc2[i][1]);
        v[4] = lo32(acc2[i][2]); v[5] = hi32(acc2[i][2]);
        v[6] = lo32(acc2[i][3]); v[7] = hi32(acc2[i][3]);
#pragma unroll
        for (int j = 0; j < 8; j++) {
            float x = __fadd_rn(v[j], bb[j]);
            v[j] = do_relu ? fmaxf(x, 0.f) : x;
        }
        *(float4*)(Crow + tx * 4)      = make_float4(v[0], v[1], v[2], v[3]);
        *(float4*)(Crow + 64 + tx * 4) = make_float4(v[4], v[5], v[6], v[7]);
    }
}

// Gconv: e = bmm(Anorm, AX) + UX (dot from zero, then elementwise add).
// grid (BATCH, OUTF/256); each thread handles exactly one feature column.
__global__ void gconv_kernel(const float* __restrict__ adj,
                             const float* __restrict__ Y, float* __restrict__ e)
{
    const int b = blockIdx.x, tid = threadIdx.x;

    __shared__ float sA[NN * NN];
    __shared__ float cs[NN];
    __shared__ float An[NN][NN + 2];

    if (tid < NN * NN) sA[tid] = adj[(size_t)b * NN * NN + tid];
    __syncthreads();
    if (tid < NN) {
        float s = 0.f;
#pragma unroll
        for (int i = 0; i < NN; i++) s = __fadd_rn(s, sA[i * NN + tid]);
        cs[tid] = fmaxf(s, 1e-12f);
    }
    __syncthreads();
    if (tid < NN * NN) {
        int i = tid / NN, j = tid - i * NN;
        An[i][j] = __fdiv_rn(sA[tid], cs[j]);
    }
    __syncthreads();

    const int f = blockIdx.y * 256 + tid;   // 0..1023
    const float* Yb = Y + (size_t)b * NN * WN;
    float* eb = e + (size_t)b * NN * OUTF;

    float ax[NN], ux[NN];
#pragma unroll
    for (int j = 0; j < NN; j++) {
        ax[j] = Yb[j * WN + f];
        ux[j] = Yb[j * WN + OUTF + f];
    }
#pragma unroll
    for (int i = 0; i < NN; i++) {
        float d = __fmul_rn(An[i][0], ax[0]);
#pragma unroll
        for (int j = 1; j < NN; j++) d = fmaf(An[i][j], ax[j], d);
        eb[i * OUTF + f] = __fadd_rn(d, ux[i]);
    }
}

// Affinity gram (sequential fp32) + softmax(200*s) + 20 Sinkhorn iters with
// FTZ emulation at every tiny-value production site.
__global__ void affinity_kernel(const float* __restrict__ Mx, const float* __restrict__ E2,
                                float* __restrict__ s_out)
{
    const int b = blockIdx.x, tid = threadIdx.x;
    __shared__ float sM[NN][129];
    __shared__ float sE[NN][129];
    __shared__ float S[NN][NN + 1];

    const float* Mb = Mx + (size_t)b * NN * OUTF;
    const float* Eb = E2 + (size_t)b * NN * OUTF;
    const int i = tid / NN, j = tid - i * NN;
    float acc = 0.f;

    for (int d0 = 0; d0 < OUTF; d0 += 128) {
        for (int t = tid; t < NN * 128; t += 256) {
            int r = t >> 7, c = t & 127;
            sM[r][c] = Mb[r * OUTF + d0 + c];
            sE[r][c] = Eb[r * OUTF + d0 + c];
        }
        __syncthreads();
        if (tid < NN * NN) {
#pragma unroll 8
            for (int c = 0; c < 128; c++)
                acc = fmaf(sM[i][c], sE[j][c], acc);
        }
        __syncthreads();
    }
    if (tid < NN * NN) S[i][j] = acc;
    __syncthreads();

    if (tid < NN) {
        float t[NN], m = -__int_as_float(0x7f800000);
#pragma unroll
        for (int jj = 0; jj < NN; jj++) {
            t[jj] = __fmul_rn(200.f, S[tid][jj]);
            m = fmaxf(m, t[jj]);
        }
        float p[NN], sum = 0.f;
#pragma unroll
        for (int jj = 0; jj < NN; jj++) {
            p[jj] = ftzf(expf(__fadd_rn(t[jj], -m)));
            sum = __fadd_rn(sum, p[jj]);
        }
#pragma unroll
        for (int jj = 0; jj < NN; jj++)
            S[tid][jj] = ftzf(__fdiv_rn(p[jj], sum));
    }
    __syncthreads();

    for (int it = 0; it < 20; it++) {
        if ((it & 1) == 0) {
            if (tid < NN) {
                float sum = 0.f;
#pragma unroll
                for (int jj = 0; jj < NN; jj++) sum = __fadd_rn(sum, S[tid][jj]);
                sum = __fadd_rn(sum, 1e-10f);
#pragma unroll
                for (int jj = 0; jj < NN; jj++)
                    S[tid][jj] = ftzf(__fdiv_rn(S[tid][jj], sum));
            }
        } else {
            if (tid < NN) {
                float sum = 0.f;
#pragma unroll
                for (int ii = 0; ii < NN; ii++) sum = __fadd_rn(sum, S[ii][tid]);
                sum = __fadd_rn(sum, 1e-10f);
#pragma unroll
                for (int ii = 0; ii < NN; ii++)
                    S[ii][tid] = ftzf(__fdiv_rn(S[ii][tid], sum));
            }
        }
        __syncthreads();
    }
    if (tid < NN * NN) s_out[(size_t)b * NN * NN + tid] = S[i][j];
}

// Fusion: dot from zero over the contraction index, then add feat.
__global__ void fuse_kernel(const float* __restrict__ f1, const float* __restrict__ f2,
                            const float* __restrict__ s,
                            float* __restrict__ o1, float* __restrict__ o2)
{
    const int b = blockIdx.y;
    const int f = blockIdx.x * blockDim.x + threadIdx.x;
    __shared__ float S[NN * NN];
    if (threadIdx.x < NN * NN) S[threadIdx.x] = s[(size_t)b * NN * NN + threadIdx.x];
    __syncthreads();

    const float* f1b = f1 + (size_t)b * NN * INF;
    const float* f2b = f2 + (size_t)b * NN * INF;
    float* o1b = o1 + (size_t)b * NN * INF;
    float* o2b = o2 + (size_t)b * NN * INF;

    float x1[NN], x2[NN];
#pragma unroll
    for (int r = 0; r < NN; r++) { x1[r] = f1b[r * INF + f]; x2[r] = f2b[r * INF + f]; }
#pragma unroll
    for (int i = 0; i < NN; i++) {
        float d = __fmul_rn(S[i * NN], x2[0]);
#pragma unroll
        for (int jj = 1; jj < NN; jj++) d = fmaf(S[i * NN + jj], x2[jj], d);
        o1b[i * INF + f] = __fadd_rn(x1[i], d);
    }
#pragma unroll
    for (int jj = 0; jj < NN; jj++) {
        float d = __fmul_rn(S[jj], x1[0]);
#pragma unroll
        for (int ii = 1; ii < NN; ii++) d = fmaf(S[ii * NN + jj], x1[ii], d);
        o2b[jj * INF + f] = __fadd_rn(x2[jj], d);
    }
}

static float* symaddr(const void* sym) {
    void* p = nullptr;
    cudaGetSymbolAddress(&p, sym);
    return (float*)p;
}

extern "C" void kernel_launch(void* const* d_in, const int* in_sizes, int n_in,
                              void* d_out, int out_size)
{
    const float* feat1  = (const float*)d_in[0];
    const float* feat2  = (const float*)d_in[1];
    const float* adj    = (const float*)d_in[2];
    const float* a_fc_w = (const float*)d_in[3];
    const float* a_fc_b = (const float*)d_in[4];
    const float* u_fc_w = (const float*)d_in[5];
    const float* u_fc_b = (const float*)d_in[6];
    const float* aff_A  = (const float*)d_in[7];

    float* out   = (float*)d_out;
    float* s_out = out;
    float* out1  = out + (size_t)BATCH * NN * NN;
    float* out2  = out1 + (size_t)BATCH * NN * INF;

    float* Wp = symaddr(g_Wpack);
    float* bp = symaddr(g_bpack);
    float* Y1 = symaddr(g_Y1);
    float* Y2 = symaddr(g_Y2);
    float* e1 = symaddr(g_e1);
    float* e2 = symaddr(g_e2);
    float* M1 = symaddr(g_M1);

    // Fork/join stream for DAG overlap (host objects; created per call, never
    // destroyed -> no device memory, capture-safe, deterministic node set).
    cudaStream_t s2;
    cudaEvent_t evA, evB;
    cudaStreamCreateWithFlags(&s2, cudaStreamNonBlocking);
    cudaEventCreateWithFlags(&evA, cudaEventDisableTiming);
    cudaEventCreateWithFlags(&evB, cudaEventDisableTiming);

    pack_w_kernel<<<(INF * OUTF + 255) / 256, 256>>>(a_fc_w, a_fc_b, u_fc_w, u_fc_b);

    // fork: s2 joins after pack_w
    cudaEventRecord(evA, 0);
    cudaStreamWaitEvent(s2, evA, 0);

    dim3 g1(WN / 128, MROWS / 128);
    dim3 gg(BATCH, OUTF / 256);
    dim3 g2(OUTF / 128, MROWS / 128);

    // s0 chain: Y1 -> gconv1 -> M1   (launched first => dispatch priority)
    sgemm_kernel<<<g1, 256, 0, 0>>>(feat1, Wp, Y1, INF, WN, bp, 1);
    // s2 chain: Y2 -> gconv2         (fills SMs while s0 runs gconv1/M1)
    sgemm_kernel<<<g1, 256, 0, s2>>>(feat2, Wp, Y2, INF, WN, bp, 1);

    gconv_kernel<<<gg, 256, 0, 0>>>(adj, Y1, e1);
    gconv_kernel<<<gg, 256, 0, s2>>>(adj, Y2, e2);

    sgemm_kernel<<<g2, 256, 0, 0>>>(e1, aff_A, M1, OUTF, OUTF, nullptr, 0);

    // join: s0 waits for s2 (e2 ready)
    cudaEventRecord(evB, s2);
    cudaStreamWaitEvent(0, evB, 0);

    affinity_kernel<<<BATCH, 256>>>(M1, e2, s_out);

    dim3 g3(INF / 256, BATCH);
    fuse_kernel<<<g3, 256>>>(feat1, feat2, s_out, out1, out2);
}